// round 13
// baseline (speedup 1.0000x reference)
#include <cuda_runtime.h>
#include <cstdint>

#define NTHR 256
#define KTOT 1152
#define NBLK 36          // K blocks of 32

// smem layout (bytes) — 4-deep buffers, swizzled 128B rows
#define SM_A   0                       // 4 x (128 rows * 128B) = 64KB
#define SM_B   65536                   // 4 x (256 rows * 128B) = 128KB
#define SM_OFF 196608                  // 1152 int offsets
#define SM_TOT 201216
#define EPI_LD 132                     // epilogue [256 oc][132 m] floats = 135KB

// ---- tf32-preconverted weights (device global scratch) ----
__device__ float g_wt_tf[256u * KTOT];              // 1.18 MB

__device__ __forceinline__ uint32_t s2u(const void* p) {
    uint32_t a;
    asm("{ .reg .u64 t; cvta.to.shared.u64 t, %1; cvt.u32.u64 %0, t; }" : "=r"(a) : "l"(p));
    return a;
}

__device__ __forceinline__ void ldsm4(uint32_t* r, uint32_t addr) {
    asm volatile("ldmatrix.sync.aligned.m8n8.x4.shared.b16 {%0,%1,%2,%3}, [%4];"
        : "=r"(r[0]), "=r"(r[1]), "=r"(r[2]), "=r"(r[3]) : "r"(addr));
}

__device__ __forceinline__ float f2tf(float f) {
    uint32_t o;
    asm("cvt.rna.tf32.f32 %0, %1;" : "=r"(o) : "f"(f));
    return __uint_as_float(o);
}

__device__ __forceinline__ void mma8(float* d, const uint32_t* a, const uint32_t* b) {
    asm volatile("mma.sync.aligned.m16n8k8.row.col.f32.tf32.tf32.f32 "
        "{%0,%1,%2,%3}, {%4,%5,%6,%7}, {%8,%9}, {%0,%1,%2,%3};"
        : "+f"(d[0]), "+f"(d[1]), "+f"(d[2]), "+f"(d[3])
        : "r"(a[0]), "r"(a[1]), "r"(a[2]), "r"(a[3]), "r"(b[0]), "r"(b[1]));
}

#define CP16(dst, src) \
    asm volatile("cp.async.cg.shared.global [%0], [%1], 16;" :: "r"(dst), "l"(src) : "memory")
#define CP_COMMIT()  asm volatile("cp.async.commit_group;" ::: "memory")
#define CP_WAIT0()   asm volatile("cp.async.wait_group 0;" ::: "memory")
#define STS128(a, r) \
    asm volatile("st.shared.v4.b32 [%0], {%1,%2,%3,%4};" :: "r"(a), \
        "r"(__float_as_uint((r)[0])), "r"(__float_as_uint((r)[1])), \
        "r"(__float_as_uint((r)[2])), "r"(__float_as_uint((r)[3])) : "memory")

// ---- prepass: weights f32 -> tf32 bit patterns ----
__global__ __launch_bounds__(256) void cvt_wt_kernel(const float4* __restrict__ src) {
    float4* dst = reinterpret_cast<float4*>(g_wt_tf);
    const int n4 = (256 * KTOT) / 4;
    for (int i = blockIdx.x * blockDim.x + threadIdx.x; i < n4; i += gridDim.x * blockDim.x) {
        float4 v = src[i];
        v.x = f2tf(v.x); v.y = f2tf(v.y); v.z = f2tf(v.z); v.w = f2tf(v.w);
        dst[i] = v;
    }
}

__global__ __launch_bounds__(NTHR, 1)
void conv2d_tf32_mmasync(const float* __restrict__ in, float* __restrict__ out)
{
    extern __shared__ char smem[];
    const uint32_t sb = s2u(smem);
    float* smf = (float*)smem;
    int* offs = (int*)(smem + SM_OFF);

    const int tid = threadIdx.x;
    const int wid = tid >> 5, lane = tid & 31;
    const int n   = blockIdx.y;
    const int oh0 = blockIdx.x * 2;

    // k -> input offset table (floats): ic*4096 + kh*64 + kw
    for (int k = tid; k < KTOT; k += NTHR) {
        int ic = k / 9, t9 = k - ic * 9;
        int kh = t9 / 3, kw = t9 - kh * 3;
        offs[k] = ic * 4096 + kh * 64 + kw;
    }

    // ---- A staging: thread = (m = tid&127, k-16-group aq = tid>>7) ----
    const float* in_n = in + (size_t)n * 128 * 64 * 64;
    const float* wtp  = g_wt_tf;
    const int am = tid & 127, aq = tid >> 7;          // aq in 0..1 (16 k each)
    const int aow = am & 63;
    const float* abase = in_n + (size_t)(oh0 + (am >> 6)) * 64 + (aow < 62 ? aow : 0);
    const uint32_t axm_st = (uint32_t)(am & 7) << 4;
    uint32_t asts[2][2];                               // [k-half h][q16]
    #pragma unroll
    for (int h = 0; h < 2; h++)
        #pragma unroll
        for (int q = 0; q < 2; q++)
            asts[h][q] = (uint32_t)am * 128 +
                (((uint32_t)(aq * 64 + h * 32 + q * 16)) ^ axm_st);

    // ---- B staging: thread = (oc-block bocb = tid>>3, quad bq = tid&7) ----
    const int bq = tid & 7, bocb = tid >> 3;          // bocb in 0..31
    const uint32_t bstcol = ((uint32_t)bq * 16) ^ ((uint32_t)(bocb & 7) << 4);

    // ---- warp tiling: 2x4 grid, warp tile m64 x n64 ----
    const int m0 = (wid & 1) * 64, n0 = (wid >> 1) * 64;
    const int T = lane >> 3, rowin = lane & 7;
    const uint32_t acol = (uint32_t)(T >> 1) << 4;
    const uint32_t bcol = (uint32_t)(T & 1) << 4;
    uint32_t arow[4], axm[4], brow[4], bxm[4];
    #pragma unroll
    for (int mi = 0; mi < 4; mi++) {
        int r = m0 + mi * 16 + ((T & 1) << 3) + rowin;
        arow[mi] = (uint32_t)r * 128; axm[mi] = (uint32_t)(r & 7) << 4;
    }
    #pragma unroll
    for (int nb = 0; nb < 4; nb++) {
        int r = n0 + nb * 16 + ((T >> 1) << 3) + rowin;
        brow[nb] = (uint32_t)r * 128; bxm[nb] = (uint32_t)(r & 7) << 4;
    }

    float acc[4][8][4];
    #pragma unroll
    for (int i = 0; i < 4; i++)
        #pragma unroll
        for (int j = 0; j < 8; j++)
            #pragma unroll
            for (int v = 0; v < 4; v++) acc[i][j][v] = 0.0f;

    __syncthreads();   // offs table ready

    // staging helpers (macros to keep regs simple)
    float ar[8];
#define LDG_A(blk, h) { const int kb = (blk) * 32 + aq * 16 + (h) * 8;          \
    _Pragma("unroll") for (int j = 0; j < 8; j++) ar[j] = abase[offs[kb + j]]; }
#define STS_A(blk, h) { _Pragma("unroll") for (int j = 0; j < 8; j++) ar[j] = f2tf(ar[j]); \
    const uint32_t As_ = sb + SM_A + (uint32_t)((blk) & 3) * 16384;             \
    STS128(As_ + asts[h][0], ar); STS128(As_ + asts[h][1], ar + 4); }
#define CP_B(blk) { const uint32_t Bs_ = sb + SM_B + (uint32_t)((blk) & 3) * 32768; \
    _Pragma("unroll") for (int j = 0; j < 8; j++) { int oc = j * 32 + bocb;     \
        CP16(Bs_ + (uint32_t)oc * 128 + bstcol,                                 \
             wtp + (size_t)oc * KTOT + (blk) * 32 + bq * 4); } }

#define LDSM_STEP(A_, B_, As_, Bs_, s) {                                        \
    _Pragma("unroll") for (int mi = 0; mi < 4; mi++)                            \
        ldsm4(A_[mi], (As_) + arow[mi] + ((acol | ((uint32_t)(s) << 5)) ^ axm[mi])); \
    _Pragma("unroll") for (int nb = 0; nb < 4; nb++)                            \
        ldsm4(B_[nb], (Bs_) + brow[nb] + ((bcol | ((uint32_t)(s) << 5)) ^ bxm[nb])); }

#define MMA_STEP(A_, B_) {                                                      \
    _Pragma("unroll") for (int mi = 0; mi < 4; mi++)                            \
        _Pragma("unroll") for (int nb = 0; nb < 4; nb++) {                      \
            mma8(acc[mi][2 * nb],     A_[mi], &B_[nb][0]);                      \
            mma8(acc[mi][2 * nb + 1], A_[mi], &B_[nb][2]); } }

    // ---- prologue: stage blocks 0 and 1 ----
    #pragma unroll
    for (int blk = 0; blk < 2; blk++) {
        LDG_A(blk, 0); STS_A(blk, 0);
        LDG_A(blk, 1); STS_A(blk, 1);
        CP_B(blk);
    }
    CP_COMMIT();
    CP_WAIT0();
    __syncthreads();

    uint32_t af0[4][4], bf0[4][4], af1[4][4], bf1[4][4];

    #pragma unroll 1
    for (int j2 = 0; j2 < NBLK; j2 += 2) {
        const bool more = (j2 + 2 < NBLK);
        const uint32_t As0 = sb + SM_A + (uint32_t)(j2 & 3) * 16384;
        const uint32_t Bs0 = sb + SM_B + (uint32_t)(j2 & 3) * 32768;
        const uint32_t As1 = sb + SM_A + (uint32_t)((j2 + 1) & 3) * 16384;
        const uint32_t Bs1 = sb + SM_B + (uint32_t)((j2 + 1) & 3) * 32768;

        if (more) { CP_B(j2 + 2); CP_B(j2 + 3); CP_COMMIT(); }

        LDSM_STEP(af0, bf0, As0, Bs0, 0);
        if (more) LDG_A(j2 + 2, 0);

        LDSM_STEP(af1, bf1, As0, Bs0, 1);  MMA_STEP(af0, bf0);
        LDSM_STEP(af0, bf0, As0, Bs0, 2);  MMA_STEP(af1, bf1);

        if (more) { STS_A(j2 + 2, 0); LDG_A(j2 + 2, 1); }

        LDSM_STEP(af1, bf1, As0, Bs0, 3);  MMA_STEP(af0, bf0);

        if (more) { STS_A(j2 + 2, 1); LDG_A(j2 + 3, 0); }

        LDSM_STEP(af0, bf0, As1, Bs1, 0);  MMA_STEP(af1, bf1);
        LDSM_STEP(af1, bf1, As1, Bs1, 1);  MMA_STEP(af0, bf0);

        if (more) { STS_A(j2 + 3, 0); LDG_A(j2 + 3, 1); }

        LDSM_STEP(af0, bf0, As1, Bs1, 2);  MMA_STEP(af1, bf1);
        LDSM_STEP(af1, bf1, As1, Bs1, 3);  MMA_STEP(af0, bf0);

        if (more) STS_A(j2 + 3, 1);

        MMA_STEP(af1, bf1);

        if (more) CP_WAIT0();
        __syncthreads();      // single barrier per 2-block stage
    }

    // ---- epilogue: full 256-oc transpose in smem, float2 stores (8B-aligned) ----
    const int eg = lane >> 2, ee = lane & 3;
    #pragma unroll
    for (int mi = 0; mi < 4; mi++)
        #pragma unroll
        for (int nj = 0; nj < 8; nj++) {
            int oc  = n0 + nj * 8 + 2 * ee;
            int mm  = m0 + mi * 16 + eg;
            smf[oc * EPI_LD + mm]           = acc[mi][nj][0];
            smf[(oc + 1) * EPI_LD + mm]     = acc[mi][nj][1];
            smf[oc * EPI_LD + mm + 8]       = acc[mi][nj][2];
            smf[(oc + 1) * EPI_LD + mm + 8] = acc[mi][nj][3];
        }
    __syncthreads();
    // 512 output rows (oc, oh-local); 2 rows per thread; float2 stores
    // (row start = ...*3844 + oh*62 floats: always even, never 4-aligned for odd oh)
    #pragma unroll
    for (int p = 0; p < 2; p++) {
        int r   = p * NTHR + tid;
        int oc  = r >> 1, ohl = r & 1;
        const float* srow = smf + oc * EPI_LD + ohl * 64;
        float* orow = out + ((size_t)n * 256 + oc) * 3844 + (size_t)(oh0 + ohl) * 62;
        #pragma unroll
        for (int j = 0; j < 31; j++)
            *reinterpret_cast<float2*>(orow + 2 * j) =
                *reinterpret_cast<const float2*>(srow + 2 * j);
    }
}

extern "C" void kernel_launch(void* const* d_in, const int* in_sizes, int n_in,
                              void* d_out, int out_size)
{
    const float* in = (const float*)d_in[0];   // [32,128,64,64]
    const float* wt = (const float*)d_in[1];   // [256,128,3,3]
    float* out = (float*)d_out;                // [32,256,62,62]

    // prepass: convert weights to tf32 bit patterns (input cvt fused into main)
    cvt_wt_kernel<<<288, 256>>>(reinterpret_cast<const float4*>(wt));

    cudaFuncSetAttribute(conv2d_tf32_mmasync,
                         cudaFuncAttributeMaxDynamicSharedMemorySize, SM_TOT);
    dim3 grid(31, 32);
    conv2d_tf32_mmasync<<<grid, NTHR, SM_TOT>>>(in, out);
}

// round 14
// speedup vs baseline: 1.0641x; 1.0641x over previous
#include <cuda_runtime.h>
#include <cstdint>

#define NTHR 512
#define KTOT 1152
#define NBLK 36          // K blocks of 32

// smem layout (bytes) — 4-deep buffers, swizzled 128B rows
#define SM_A   0                       // 4 x (128 rows * 128B) = 64KB
#define SM_B   65536                   // 4 x (256 rows * 128B) = 128KB
#define SM_OFF 196608                  // 1152 int offsets
#define SM_TOT 201216
#define EPI_LD 132                     // epilogue [256 oc][132 m] floats = 135KB

// ---- tf32-preconverted weights (device global scratch) ----
__device__ float g_wt_tf[256u * KTOT];              // 1.18 MB

__device__ __forceinline__ uint32_t s2u(const void* p) {
    uint32_t a;
    asm("{ .reg .u64 t; cvta.to.shared.u64 t, %1; cvt.u32.u64 %0, t; }" : "=r"(a) : "l"(p));
    return a;
}

__device__ __forceinline__ void ldsm4(uint32_t* r, uint32_t addr) {
    asm volatile("ldmatrix.sync.aligned.m8n8.x4.shared.b16 {%0,%1,%2,%3}, [%4];"
        : "=r"(r[0]), "=r"(r[1]), "=r"(r[2]), "=r"(r[3]) : "r"(addr));
}

__device__ __forceinline__ float f2tf(float f) {
    uint32_t o;
    asm("cvt.rna.tf32.f32 %0, %1;" : "=r"(o) : "f"(f));
    return __uint_as_float(o);
}

__device__ __forceinline__ void mma8(float* d, const uint32_t* a, const uint32_t* b) {
    asm volatile("mma.sync.aligned.m16n8k8.row.col.f32.tf32.tf32.f32 "
        "{%0,%1,%2,%3}, {%4,%5,%6,%7}, {%8,%9}, {%0,%1,%2,%3};"
        : "+f"(d[0]), "+f"(d[1]), "+f"(d[2]), "+f"(d[3])
        : "r"(a[0]), "r"(a[1]), "r"(a[2]), "r"(a[3]), "r"(b[0]), "r"(b[1]));
}

#define CP16(dst, src) \
    asm volatile("cp.async.cg.shared.global [%0], [%1], 16;" :: "r"(dst), "l"(src) : "memory")
#define CP_COMMIT()  asm volatile("cp.async.commit_group;" ::: "memory")
#define CP_WAIT0()   asm volatile("cp.async.wait_group 0;" ::: "memory")
#define STS128(a, r) \
    asm volatile("st.shared.v4.b32 [%0], {%1,%2,%3,%4};" :: "r"(a), \
        "r"(__float_as_uint((r)[0])), "r"(__float_as_uint((r)[1])), \
        "r"(__float_as_uint((r)[2])), "r"(__float_as_uint((r)[3])) : "memory")

// ---- prepass: weights f32 -> tf32 bit patterns ----
__global__ __launch_bounds__(256) void cvt_wt_kernel(const float4* __restrict__ src) {
    float4* dst = reinterpret_cast<float4*>(g_wt_tf);
    const int n4 = (256 * KTOT) / 4;
    for (int i = blockIdx.x * blockDim.x + threadIdx.x; i < n4; i += gridDim.x * blockDim.x) {
        float4 v = src[i];
        v.x = f2tf(v.x); v.y = f2tf(v.y); v.z = f2tf(v.z); v.w = f2tf(v.w);
        dst[i] = v;
    }
}

__global__ __launch_bounds__(NTHR, 1)
void conv2d_tf32_mmasync(const float* __restrict__ in, float* __restrict__ out)
{
    extern __shared__ char smem[];
    const uint32_t sb = s2u(smem);
    float* smf = (float*)smem;
    int* offs = (int*)(smem + SM_OFF);

    const int tid = threadIdx.x;
    const int wid = tid >> 5, lane = tid & 31;
    const int n   = blockIdx.y;
    const int oh0 = blockIdx.x * 2;

    // k -> input offset table (floats): ic*4096 + kh*64 + kw
    for (int k = tid; k < KTOT; k += NTHR) {
        int ic = k / 9, t9 = k - ic * 9;
        int kh = t9 / 3, kw = t9 - kh * 3;
        offs[k] = ic * 4096 + kh * 64 + kw;
    }

    // ---- A staging: thread = (m = tid&127, k-octet aq = tid>>7) ----
    const float* in_n = in + (size_t)n * 128 * 64 * 64;
    const float* wtp  = g_wt_tf;
    const int am = tid & 127, aq = tid >> 7;          // aq in 0..3
    const int aow = am & 63;
    const float* abase = in_n + (size_t)(oh0 + (am >> 6)) * 64 + (aow < 62 ? aow : 0);
    const uint32_t axm_st  = (uint32_t)(am & 7) << 4;
    const uint32_t asts0 = (uint32_t)am * 128 + (((uint32_t)aq * 32)      ^ axm_st);
    const uint32_t asts1 = (uint32_t)am * 128 + (((uint32_t)aq * 32 + 16) ^ axm_st);

    // ---- B staging: thread = (oc-block bocb = tid>>3, quad bq = tid&7) ----
    const int bq = tid & 7, bocb = tid >> 3;          // bocb in 0..63
    const uint32_t bstcol = ((uint32_t)bq * 16) ^ ((uint32_t)(bocb & 7) << 4);

    // ---- warp tiling: 4x4 grid, warp tile m32 x n64 ----
    const int m0 = (wid & 3) * 32, n0 = (wid >> 2) * 64;
    const int T = lane >> 3, rowin = lane & 7;
    const uint32_t acol = (uint32_t)(T >> 1) << 4;
    const uint32_t bcol = (uint32_t)(T & 1) << 4;
    uint32_t arow[2], axm[2], brow[4], bxm[4];
    #pragma unroll
    for (int mi = 0; mi < 2; mi++) {
        int r = m0 + mi * 16 + ((T & 1) << 3) + rowin;
        arow[mi] = (uint32_t)r * 128; axm[mi] = (uint32_t)(r & 7) << 4;
    }
    #pragma unroll
    for (int nb = 0; nb < 4; nb++) {
        int r = n0 + nb * 16 + ((T >> 1) << 3) + rowin;
        brow[nb] = (uint32_t)r * 128; bxm[nb] = (uint32_t)(r & 7) << 4;
    }

    float acc[2][8][4];
    #pragma unroll
    for (int i = 0; i < 2; i++)
        #pragma unroll
        for (int j = 0; j < 8; j++)
            #pragma unroll
            for (int v = 0; v < 4; v++) acc[i][j][v] = 0.0f;

    __syncthreads();   // offs table ready

    float ar[8];
    // ---- prologue: stage blocks 0 and 1 into buffers 0,1 ----
    #pragma unroll
    for (int blk = 0; blk < 2; blk++) {
        const int kb = blk * 32 + aq * 8;
        #pragma unroll
        for (int j = 0; j < 8; j++) ar[j] = f2tf(abase[offs[kb + j]]);
        const uint32_t Bs = sb + SM_B + (uint32_t)blk * 32768;
        #pragma unroll
        for (int j = 0; j < 4; j++) {
            int oc = j * 64 + bocb;
            CP16(Bs + (uint32_t)oc * 128 + bstcol,
                 wtp + (size_t)oc * KTOT + blk * 32 + bq * 4);
        }
        const uint32_t As = sb + SM_A + (uint32_t)blk * 16384;
        STS128(As + asts0, ar);
        STS128(As + asts1, ar + 4);
    }
    CP_COMMIT();
    CP_WAIT0();
    __syncthreads();

    #pragma unroll 1
    for (int j2 = 0; j2 < NBLK; j2 += 2) {
        const bool more = (j2 + 2 < NBLK);

        // issue B cp.async for blocks j2+2, j2+3 and A LDG for block j2+2
        if (more) {
            #pragma unroll
            for (int blk = 0; blk < 2; blk++) {
                const int jb = j2 + 2 + blk;
                const uint32_t Bs = sb + SM_B + (uint32_t)(jb & 3) * 32768;
                #pragma unroll
                for (int j = 0; j < 4; j++) {
                    int oc = j * 64 + bocb;
                    CP16(Bs + (uint32_t)oc * 128 + bstcol,
                         wtp + (size_t)oc * KTOT + jb * 32 + bq * 4);
                }
            }
            CP_COMMIT();
            const int kb = (j2 + 2) * 32 + aq * 8;
            #pragma unroll
            for (int j = 0; j < 8; j++) ar[j] = abase[offs[kb + j]];
        }

        // ---- compute block j2 ----
        {
            const uint32_t As = sb + SM_A + (uint32_t)(j2 & 3) * 16384;
            const uint32_t Bs = sb + SM_B + (uint32_t)(j2 & 3) * 32768;
            #pragma unroll
            for (int s = 0; s < 4; s++) {
                uint32_t a[2][4], b[4][4];
                #pragma unroll
                for (int mi = 0; mi < 2; mi++)
                    ldsm4(a[mi], As + arow[mi] + ((acol | ((uint32_t)s << 5)) ^ axm[mi]));
                #pragma unroll
                for (int nb = 0; nb < 4; nb++)
                    ldsm4(b[nb], Bs + brow[nb] + ((bcol | ((uint32_t)s << 5)) ^ bxm[nb]));
                #pragma unroll
                for (int mi = 0; mi < 2; mi++)
                    #pragma unroll
                    for (int nb = 0; nb < 4; nb++) {
                        mma8(acc[mi][2 * nb],     a[mi], &b[nb][0]);
                        mma8(acc[mi][2 * nb + 1], a[mi], &b[nb][2]);
                    }
            }
        }

        // cvt + store A block j2+2, load A block j2+3
        if (more) {
            #pragma unroll
            for (int j = 0; j < 8; j++) ar[j] = f2tf(ar[j]);
            const uint32_t An = sb + SM_A + (uint32_t)((j2 + 2) & 3) * 16384;
            STS128(An + asts0, ar);
            STS128(An + asts1, ar + 4);
            const int kb = (j2 + 3) * 32 + aq * 8;
            #pragma unroll
            for (int j = 0; j < 8; j++) ar[j] = abase[offs[kb + j]];
        }

        // ---- compute block j2+1 ----
        {
            const uint32_t As = sb + SM_A + (uint32_t)((j2 + 1) & 3) * 16384;
            const uint32_t Bs = sb + SM_B + (uint32_t)((j2 + 1) & 3) * 32768;
            #pragma unroll
            for (int s = 0; s < 4; s++) {
                uint32_t a[2][4], b[4][4];
                #pragma unroll
                for (int mi = 0; mi < 2; mi++)
                    ldsm4(a[mi], As + arow[mi] + ((acol | ((uint32_t)s << 5)) ^ axm[mi]));
                #pragma unroll
                for (int nb = 0; nb < 4; nb++)
                    ldsm4(b[nb], Bs + brow[nb] + ((bcol | ((uint32_t)s << 5)) ^ bxm[nb]));
                #pragma unroll
                for (int mi = 0; mi < 2; mi++)
                    #pragma unroll
                    for (int nb = 0; nb < 4; nb++) {
                        mma8(acc[mi][2 * nb],     a[mi], &b[nb][0]);
                        mma8(acc[mi][2 * nb + 1], a[mi], &b[nb][2]);
                    }
            }
        }

        if (more) {
            #pragma unroll
            for (int j = 0; j < 8; j++) ar[j] = f2tf(ar[j]);
            const uint32_t An = sb + SM_A + (uint32_t)((j2 + 3) & 3) * 16384;
            STS128(An + asts0, ar);
            STS128(An + asts1, ar + 4);
            CP_WAIT0();
        }
        __syncthreads();      // single barrier per 2-block stage
    }

    // ---- epilogue: full 256-oc transpose in smem, 1 barrier ----
    const int eg = lane >> 2, ee = lane & 3;
    #pragma unroll
    for (int mi = 0; mi < 2; mi++)
        #pragma unroll
        for (int nj = 0; nj < 8; nj++) {
            int oc  = n0 + nj * 8 + 2 * ee;
            int mm  = m0 + mi * 16 + eg;
            smf[oc * EPI_LD + mm]           = acc[mi][nj][0];
            smf[(oc + 1) * EPI_LD + mm]     = acc[mi][nj][1];
            smf[oc * EPI_LD + mm + 8]       = acc[mi][nj][2];
            smf[(oc + 1) * EPI_LD + mm + 8] = acc[mi][nj][3];
        }
    __syncthreads();
    // 512 output rows (oc, oh-local) = 512 threads: 1 row each, float2 stores
    // (row start in floats = (n*256+oc)*3844 + oh*62: always even -> 8B-aligned)
    {
        int oc  = tid >> 1, ohl = tid & 1;
        const float* srow = smf + oc * EPI_LD + ohl * 64;
        float* orow = out + ((size_t)n * 256 + oc) * 3844 + (size_t)(oh0 + ohl) * 62;
        #pragma unroll
        for (int j = 0; j < 31; j++)
            *reinterpret_cast<float2*>(orow + 2 * j) =
                *reinterpret_cast<const float2*>(srow + 2 * j);
    }
}

extern "C" void kernel_launch(void* const* d_in, const int* in_sizes, int n_in,
                              void* d_out, int out_size)
{
    const float* in = (const float*)d_in[0];   // [32,128,64,64]
    const float* wt = (const float*)d_in[1];   // [256,128,3,3]
    float* out = (float*)d_out;                // [32,256,62,62]

    // prepass: convert weights to tf32 bit patterns (input cvt fused into main)
    cvt_wt_kernel<<<288, 256>>>(reinterpret_cast<const float4*>(wt));

    cudaFuncSetAttribute(conv2d_tf32_mmasync,
                         cudaFuncAttributeMaxDynamicSharedMemorySize, SM_TOT);
    dim3 grid(31, 32);
    conv2d_tf32_mmasync<<<grid, NTHR, SM_TOT>>>(in, out);
}

// round 15
// speedup vs baseline: 1.2712x; 1.1947x over previous
#include <cuda_runtime.h>
#include <cstdint>

#define NTHR 512
#define KTOT 1152
#define NBLK 36          // K blocks of 32

// smem layout (bytes) — 4-deep buffers, swizzled 128B rows
#define SM_A   0                       // 4 x (128 rows * 128B) = 64KB
#define SM_B   65536                   // 4 x (256 rows * 128B) = 128KB
#define SM_OFF 196608                  // 1152 int offsets
#define SM_TOT 201216
#define EPI_LD 132                     // epilogue [256 oc][132 m] floats = 135KB

// ---- tf32-preconverted weights (device global scratch) ----
__device__ float g_wt_tf[256u * KTOT];              // 1.18 MB

__device__ __forceinline__ uint32_t s2u(const void* p) {
    uint32_t a;
    asm("{ .reg .u64 t; cvta.to.shared.u64 t, %1; cvt.u32.u64 %0, t; }" : "=r"(a) : "l"(p));
    return a;
}

__device__ __forceinline__ void ldsm4(uint32_t* r, uint32_t addr) {
    asm volatile("ldmatrix.sync.aligned.m8n8.x4.shared.b16 {%0,%1,%2,%3}, [%4];"
        : "=r"(r[0]), "=r"(r[1]), "=r"(r[2]), "=r"(r[3]) : "r"(addr));
}

__device__ __forceinline__ float f2tf(float f) {
    uint32_t o;
    asm("cvt.rna.tf32.f32 %0, %1;" : "=r"(o) : "f"(f));
    return __uint_as_float(o);
}

__device__ __forceinline__ void mma8(float* d, const uint32_t* a, const uint32_t* b) {
    asm volatile("mma.sync.aligned.m16n8k8.row.col.f32.tf32.tf32.f32 "
        "{%0,%1,%2,%3}, {%4,%5,%6,%7}, {%8,%9}, {%0,%1,%2,%3};"
        : "+f"(d[0]), "+f"(d[1]), "+f"(d[2]), "+f"(d[3])
        : "r"(a[0]), "r"(a[1]), "r"(a[2]), "r"(a[3]), "r"(b[0]), "r"(b[1]));
}

#define CP16(dst, src) \
    asm volatile("cp.async.cg.shared.global [%0], [%1], 16;" :: "r"(dst), "l"(src) : "memory")
#define CP_COMMIT()  asm volatile("cp.async.commit_group;" ::: "memory")
#define CP_WAIT0()   asm volatile("cp.async.wait_group 0;" ::: "memory")
#define STS128(a, r) \
    asm volatile("st.shared.v4.b32 [%0], {%1,%2,%3,%4};" :: "r"(a), \
        "r"(__float_as_uint((r)[0])), "r"(__float_as_uint((r)[1])), \
        "r"(__float_as_uint((r)[2])), "r"(__float_as_uint((r)[3])) : "memory")

// ---- prepass: weights f32 -> tf32 bit patterns ----
__global__ __launch_bounds__(256) void cvt_wt_kernel(const float4* __restrict__ src) {
    float4* dst = reinterpret_cast<float4*>(g_wt_tf);
    const int n4 = (256 * KTOT) / 4;
    for (int i = blockIdx.x * blockDim.x + threadIdx.x; i < n4; i += gridDim.x * blockDim.x) {
        float4 v = src[i];
        v.x = f2tf(v.x); v.y = f2tf(v.y); v.z = f2tf(v.z); v.w = f2tf(v.w);
        dst[i] = v;
    }
}

__global__ __launch_bounds__(NTHR, 1)
void conv2d_tf32_mmasync(const float* __restrict__ in, float* __restrict__ out)
{
    extern __shared__ char smem[];
    const uint32_t sb = s2u(smem);
    float* smf = (float*)smem;
    int* offs = (int*)(smem + SM_OFF);

    const int tid = threadIdx.x;
    const int wid = tid >> 5, lane = tid & 31;
    const int n   = blockIdx.y;
    const int oh0 = blockIdx.x * 2;

    // k -> input offset table (floats): ic*4096 + kh*64 + kw
    for (int k = tid; k < KTOT; k += NTHR) {
        int ic = k / 9, t9 = k - ic * 9;
        int kh = t9 / 3, kw = t9 - kh * 3;
        offs[k] = ic * 4096 + kh * 64 + kw;
    }

    // ---- A staging: thread = (m = tid&127, k-octet aq = tid>>7) ----
    const float* in_n = in + (size_t)n * 128 * 64 * 64;
    const float* wtp  = g_wt_tf;
    const int am = tid & 127, aq = tid >> 7;          // aq in 0..3
    const int aow = am & 63;
    const float* abase = in_n + (size_t)(oh0 + (am >> 6)) * 64 + (aow < 62 ? aow : 0);
    const uint32_t axm_st  = (uint32_t)(am & 7) << 4;
    const uint32_t asts0 = (uint32_t)am * 128 + (((uint32_t)aq * 32)      ^ axm_st);
    const uint32_t asts1 = (uint32_t)am * 128 + (((uint32_t)aq * 32 + 16) ^ axm_st);

    // ---- B staging: thread = (oc-block bocb = tid>>3, quad bq = tid&7) ----
    const int bq = tid & 7, bocb = tid >> 3;          // bocb in 0..63
    const uint32_t bstcol = ((uint32_t)bq * 16) ^ ((uint32_t)(bocb & 7) << 4);

    // ---- warp tiling: 4x4 grid, warp tile m32 x n64 ----
    const int m0 = (wid & 3) * 32, n0 = (wid >> 2) * 64;
    const int T = lane >> 3, rowin = lane & 7;
    const uint32_t acol = (uint32_t)(T >> 1) << 4;
    const uint32_t bcol = (uint32_t)(T & 1) << 4;
    uint32_t arow[2], axm[2], brow[4], bxm[4];
    #pragma unroll
    for (int mi = 0; mi < 2; mi++) {
        int r = m0 + mi * 16 + ((T & 1) << 3) + rowin;
        arow[mi] = (uint32_t)r * 128; axm[mi] = (uint32_t)(r & 7) << 4;
    }
    #pragma unroll
    for (int nb = 0; nb < 4; nb++) {
        int r = n0 + nb * 16 + ((T >> 1) << 3) + rowin;
        brow[nb] = (uint32_t)r * 128; bxm[nb] = (uint32_t)(r & 7) << 4;
    }

    float acc[2][8][4];
    #pragma unroll
    for (int i = 0; i < 2; i++)
        #pragma unroll
        for (int j = 0; j < 8; j++)
            #pragma unroll
            for (int v = 0; v < 4; v++) acc[i][j][v] = 0.0f;

    __syncthreads();   // offs table ready

    float ar[8];
    // ---- prologue: stage blocks 0 and 1 into buffers 0,1 ----
    #pragma unroll
    for (int blk = 0; blk < 2; blk++) {
        const int kb = blk * 32 + aq * 8;
        const int4 o0 = *reinterpret_cast<const int4*>(&offs[kb]);
        const int4 o1 = *reinterpret_cast<const int4*>(&offs[kb + 4]);
        ar[0] = f2tf(abase[o0.x]); ar[1] = f2tf(abase[o0.y]);
        ar[2] = f2tf(abase[o0.z]); ar[3] = f2tf(abase[o0.w]);
        ar[4] = f2tf(abase[o1.x]); ar[5] = f2tf(abase[o1.y]);
        ar[6] = f2tf(abase[o1.z]); ar[7] = f2tf(abase[o1.w]);
        const uint32_t Bs = sb + SM_B + (uint32_t)blk * 32768;
        #pragma unroll
        for (int j = 0; j < 4; j++) {
            int oc = j * 64 + bocb;
            CP16(Bs + (uint32_t)oc * 128 + bstcol,
                 wtp + (size_t)oc * KTOT + blk * 32 + bq * 4);
        }
        const uint32_t As = sb + SM_A + (uint32_t)blk * 16384;
        STS128(As + asts0, ar);
        STS128(As + asts1, ar + 4);
    }
    CP_COMMIT();
    CP_WAIT0();
    __syncthreads();

    #pragma unroll 1
    for (int j2 = 0; j2 < NBLK; j2 += 2) {
        const bool more = (j2 + 2 < NBLK);

        // issue B cp.async for blocks j2+2, j2+3 and A LDG for block j2+2
        if (more) {
            #pragma unroll
            for (int blk = 0; blk < 2; blk++) {
                const int jb = j2 + 2 + blk;
                const uint32_t Bs = sb + SM_B + (uint32_t)(jb & 3) * 32768;
                #pragma unroll
                for (int j = 0; j < 4; j++) {
                    int oc = j * 64 + bocb;
                    CP16(Bs + (uint32_t)oc * 128 + bstcol,
                         wtp + (size_t)oc * KTOT + jb * 32 + bq * 4);
                }
            }
            CP_COMMIT();
            const int kb = (j2 + 2) * 32 + aq * 8;
            const int4 o0 = *reinterpret_cast<const int4*>(&offs[kb]);
            const int4 o1 = *reinterpret_cast<const int4*>(&offs[kb + 4]);
            ar[0] = abase[o0.x]; ar[1] = abase[o0.y];
            ar[2] = abase[o0.z]; ar[3] = abase[o0.w];
            ar[4] = abase[o1.x]; ar[5] = abase[o1.y];
            ar[6] = abase[o1.z]; ar[7] = abase[o1.w];
        }

        // ---- compute block j2 ----
        {
            const uint32_t As = sb + SM_A + (uint32_t)(j2 & 3) * 16384;
            const uint32_t Bs = sb + SM_B + (uint32_t)(j2 & 3) * 32768;
            #pragma unroll
            for (int s = 0; s < 4; s++) {
                uint32_t a[2][4], b[4][4];
                #pragma unroll
                for (int mi = 0; mi < 2; mi++)
                    ldsm4(a[mi], As + arow[mi] + ((acol | ((uint32_t)s << 5)) ^ axm[mi]));
                #pragma unroll
                for (int nb = 0; nb < 4; nb++)
                    ldsm4(b[nb], Bs + brow[nb] + ((bcol | ((uint32_t)s << 5)) ^ bxm[nb]));
                #pragma unroll
                for (int mi = 0; mi < 2; mi++)
                    #pragma unroll
                    for (int nb = 0; nb < 4; nb++) {
                        mma8(acc[mi][2 * nb],     a[mi], &b[nb][0]);
                        mma8(acc[mi][2 * nb + 1], a[mi], &b[nb][2]);
                    }
            }
        }

        // cvt + store A block j2+2, load A block j2+3
        if (more) {
            #pragma unroll
            for (int j = 0; j < 8; j++) ar[j] = f2tf(ar[j]);
            const uint32_t An = sb + SM_A + (uint32_t)((j2 + 2) & 3) * 16384;
            STS128(An + asts0, ar);
            STS128(An + asts1, ar + 4);
            const int kb = (j2 + 3) * 32 + aq * 8;
            const int4 o0 = *reinterpret_cast<const int4*>(&offs[kb]);
            const int4 o1 = *reinterpret_cast<const int4*>(&offs[kb + 4]);
            ar[0] = abase[o0.x]; ar[1] = abase[o0.y];
            ar[2] = abase[o0.z]; ar[3] = abase[o0.w];
            ar[4] = abase[o1.x]; ar[5] = abase[o1.y];
            ar[6] = abase[o1.z]; ar[7] = abase[o1.w];
        }

        // ---- compute block j2+1 ----
        {
            const uint32_t As = sb + SM_A + (uint32_t)((j2 + 1) & 3) * 16384;
            const uint32_t Bs = sb + SM_B + (uint32_t)((j2 + 1) & 3) * 32768;
            #pragma unroll
            for (int s = 0; s < 4; s++) {
                uint32_t a[2][4], b[4][4];
                #pragma unroll
                for (int mi = 0; mi < 2; mi++)
                    ldsm4(a[mi], As + arow[mi] + ((acol | ((uint32_t)s << 5)) ^ axm[mi]));
                #pragma unroll
                for (int nb = 0; nb < 4; nb++)
                    ldsm4(b[nb], Bs + brow[nb] + ((bcol | ((uint32_t)s << 5)) ^ bxm[nb]));
                #pragma unroll
                for (int mi = 0; mi < 2; mi++)
                    #pragma unroll
                    for (int nb = 0; nb < 4; nb++) {
                        mma8(acc[mi][2 * nb],     a[mi], &b[nb][0]);
                        mma8(acc[mi][2 * nb + 1], a[mi], &b[nb][2]);
                    }
            }
        }

        if (more) {
            #pragma unroll
            for (int j = 0; j < 8; j++) ar[j] = f2tf(ar[j]);
            const uint32_t An = sb + SM_A + (uint32_t)((j2 + 3) & 3) * 16384;
            STS128(An + asts0, ar);
            STS128(An + asts1, ar + 4);
            CP_WAIT0();
        }
        __syncthreads();      // single barrier per 2-block stage
    }

    // ---- epilogue: full 256-oc transpose in smem (135KB), 1 barrier ----
    const int eg = lane >> 2, ee = lane & 3;
    #pragma unroll
    for (int mi = 0; mi < 2; mi++)
        #pragma unroll
        for (int nj = 0; nj < 8; nj++) {
            int oc  = n0 + nj * 8 + 2 * ee;
            int mm  = m0 + mi * 16 + eg;
            smf[oc * EPI_LD + mm]           = acc[mi][nj][0];
            smf[(oc + 1) * EPI_LD + mm]     = acc[mi][nj][1];
            smf[oc * EPI_LD + mm + 8]       = acc[mi][nj][2];
            smf[(oc + 1) * EPI_LD + mm + 8] = acc[mi][nj][3];
        }
    __syncthreads();
    #pragma unroll 4
    for (int i = 0; i < 64; i++) {
        int idx = i * NTHR + tid;
        int mm = idx & 127, oc = idx >> 7;
        int ow = mm & 63, oh = oh0 + (mm >> 6);
        if (ow < 62)
            out[((size_t)n * 256 + oc) * 3844 + (size_t)oh * 62 + ow]
                = smf[oc * EPI_LD + mm];
    }
}

extern "C" void kernel_launch(void* const* d_in, const int* in_sizes, int n_in,
                              void* d_out, int out_size)
{
    const float* in = (const float*)d_in[0];   // [32,128,64,64]
    const float* wt = (const float*)d_in[1];   // [256,128,3,3]
    float* out = (float*)d_out;                // [32,256,62,62]

    // prepass: convert weights to tf32 bit patterns (input cvt fused into main)
    cvt_wt_kernel<<<288, 256>>>(reinterpret_cast<const float4*>(wt));

    cudaFuncSetAttribute(conv2d_tf32_mmasync,
                         cudaFuncAttributeMaxDynamicSharedMemorySize, SM_TOT);
    dim3 grid(31, 32);
    conv2d_tf32_mmasync<<<grid, NTHR, SM_TOT>>>(in, out);
}